// round 13
// baseline (speedup 1.0000x reference)
#include <cuda_runtime.h>
#include <math.h>

#define NB 2
#define LB 512
#define FB 128
#define CB 64
#define HB 12
#define DB 16
#define NL (NB*LB)               // 1024
#define NH (NB*HB)               // 24
#define FEAT 1044
#define FEATP 1088
#define INFV 100000.0f
#define SQ29V 0.47140452079103173f
#define SCALEV 0.57735026918962576f
#define TJ 64
#define ZS 68                    // z tile row stride (floats)

__device__ float g_qh[(size_t)NH*LB*DB];     // [n][h][i][d]  (q pre-scaled by SCALEV)
__device__ float g_kh[(size_t)NH*LB*DB];
__device__ float g_vh[(size_t)NH*LB*DB];
__device__ int   g_mask[NL];
__device__ float g_alpha[(size_t)NH*LB*LB];  // node logits -> unnormalized exp(alpha)
__device__ float g_inv[(size_t)NL*HB];       // 1/S per (n,i,h); 0 for invalid rows
__device__ float g_accP[(size_t)NH*LB*3];
__device__ float g_featsP[(size_t)NL*FEATP];
__device__ float g_WoutP[(size_t)FB*FEATP];
__device__ float g_y[(size_t)NL*FB];

__device__ __forceinline__ void cp_async16(void* smem_dst, const void* gmem_src) {
    unsigned s = (unsigned)__cvta_generic_to_shared(smem_dst);
    asm volatile("cp.async.cg.shared.global [%0], [%1], 16;\n" :: "r"(s), "l"(gmem_src));
}
#define CP_COMMIT() asm volatile("cp.async.commit_group;\n")
#define CP_WAIT0()  asm volatile("cp.async.wait_group 0;\n")

// ---------------------------------------------------------------------------
// A: decode mask of ambiguous serialized dtype (bool/int32/fp32).
// ---------------------------------------------------------------------------
__global__ void decode_mask_kernel(const void* __restrict__ mraw) {
    __shared__ int cnt[4];
    int t = threadIdx.x;
    if (t < 4) cnt[t] = 0;
    __syncthreads();
    const unsigned char* b = (const unsigned char*)mraw;
    unsigned char v = b[t];
    if (v) atomicAdd(&cnt[t & 3], 1);
    __syncthreads();
    int m;
    if (cnt[1] | cnt[2] | cnt[3]) {
        if (cnt[0]) m = (b[t] != 0);
        else        m = (((const float*)mraw)[t] != 0.0f);
    } else {
        if (cnt[0]) m = (((const int*)mraw)[t] != 0);
        else        m = 0;
    }
    g_mask[t] = m;
}

// ---------------------------------------------------------------------------
// A2: zero-padded Wout copy.
// ---------------------------------------------------------------------------
__global__ void prepw_kernel(const float* __restrict__ Wout) {
    int f = blockIdx.x;
    for (int k = threadIdx.x; k < FEATP; k += 256)
        g_WoutP[(size_t)f*FEATP + k] = (k < FEAT) ? Wout[(size_t)f*FEAT + k] : 0.f;
}

// ---------------------------------------------------------------------------
// B: QKV projection -> per-head layouts [n][h][idx][d]. q scaled by SCALEV.
// ---------------------------------------------------------------------------
__global__ __launch_bounds__(576) void qkv_kernel(
    const float* __restrict__ x,
    const float* __restrict__ Wq,
    const float* __restrict__ Wk,
    const float* __restrict__ Wv)
{
    __shared__ float xs[8][FB];
    int t = threadIdx.x;
    int r0 = blockIdx.x * 8;
    for (int idx = t; idx < 8*FB; idx += 576)
        xs[idx >> 7][idx & 127] = x[(size_t)r0*FB + idx];
    __syncthreads();

    int which = t / 192;
    int o = t - which*192;
    const float* W = (which == 0) ? Wq : (which == 1) ? Wk : Wv;
    float* outp    = (which == 0) ? g_qh : (which == 1) ? g_kh : g_vh;
    const float4* W4 = (const float4*)(W + (size_t)o*FB);

    float acc[8];
#pragma unroll
    for (int r = 0; r < 8; r++) acc[r] = 0.f;
    for (int kk = 0; kk < FB/4; kk++) {
        float4 w = __ldg(&W4[kk]);
#pragma unroll
        for (int r = 0; r < 8; r++) {
            float4 xv = *(const float4*)&xs[r][kk*4];
            acc[r] += w.x*xv.x + w.y*xv.y + w.z*xv.z + w.w*xv.w;
        }
    }
    float scale = (which == 0) ? SCALEV : 1.0f;
    int h = o >> 4, d = o & 15;
#pragma unroll
    for (int r = 0; r < 8; r++) {
        int row = r0 + r;
        int n = row >> 9, i = row & 511;
        outp[((size_t)(n*HB + h)*LB + i)*DB + d] = acc[r] * scale;
    }
}

// ---------------------------------------------------------------------------
// C1: node logits GEMM. Per (n,h): [512x16]x[16x512] -> g_alpha (scaled dots).
// ---------------------------------------------------------------------------
__global__ __launch_bounds__(256) void qk_kernel()
{
    __shared__ float Qs[64*17], Ks[64*17];
    int b = blockIdx.x;
    int nh = b >> 6, tile = b & 63;
    int i0 = (tile >> 3)*64, j0 = (tile & 7)*64;
    int t = threadIdx.x;
    {
        int r = t >> 2, c4 = t & 3;
        float4 qv = *(const float4*)(g_qh + ((size_t)nh*LB + i0 + r)*DB + c4*4);
        Qs[r*17+c4*4+0]=qv.x; Qs[r*17+c4*4+1]=qv.y; Qs[r*17+c4*4+2]=qv.z; Qs[r*17+c4*4+3]=qv.w;
        float4 kv = *(const float4*)(g_kh + ((size_t)nh*LB + j0 + r)*DB + c4*4);
        Ks[r*17+c4*4+0]=kv.x; Ks[r*17+c4*4+1]=kv.y; Ks[r*17+c4*4+2]=kv.z; Ks[r*17+c4*4+3]=kv.w;
    }
    __syncthreads();
    int ti = t >> 4, tj = t & 15;
    float acc[4][4];
#pragma unroll
    for (int a = 0; a < 4; a++)
#pragma unroll
        for (int bb = 0; bb < 4; bb++) acc[a][bb] = 0.f;
    const float* Qb = Qs + (ti*4)*17;
    const float* Kb = Ks + (tj*4)*17;
#pragma unroll
    for (int d = 0; d < 16; d++) {
        float q0=Qb[d], q1=Qb[17+d], q2=Qb[34+d], q3=Qb[51+d];
        float k0=Kb[d], k1=Kb[17+d], k2=Kb[34+d], k3=Kb[51+d];
        acc[0][0]+=q0*k0; acc[0][1]+=q0*k1; acc[0][2]+=q0*k2; acc[0][3]+=q0*k3;
        acc[1][0]+=q1*k0; acc[1][1]+=q1*k1; acc[1][2]+=q1*k2; acc[1][3]+=q1*k3;
        acc[2][0]+=q2*k0; acc[2][1]+=q2*k1; acc[2][2]+=q2*k2; acc[2][3]+=q2*k3;
        acc[3][0]+=q3*k0; acc[3][1]+=q3*k1; acc[3][2]+=q3*k2; acc[3][3]+=q3*k3;
    }
    float* outb = g_alpha + ((size_t)nh*LB + i0 + ti*4)*LB + j0 + tj*4;
#pragma unroll
    for (int k = 0; k < 4; k++) {
        float4 o = make_float4(acc[k][0], acc[k][1], acc[k][2], acc[k][3]);
        *(float4*)(outb + (size_t)k*LB) = o;
    }
}

// ---------------------------------------------------------------------------
// C2: FUSED single-z-read pipeline per (n,i). Per 64-j tile (cp.async double
// buffered): logits -> exp (max-free, deferred normalization) -> e·z
// accumulation, all against the prefetched smem tile. z read from DRAM once.
// Warp w owns j-rows w*8..w*8+7 in both phases -> only __syncwarp between.
// ---------------------------------------------------------------------------
__global__ __launch_bounds__(256, 3) void fused_pz_kernel(
    const float* __restrict__ pCB,
    const float* __restrict__ z,
    const float* __restrict__ Wpb,
    const float* __restrict__ gamma_raw)
{
    __shared__ __align__(16) float zb[2][TJ*ZS];   // 2 x 17.4 KB
    __shared__ __align__(16) float lg[TJ*HB];      // e tile [jl][12], 3 KB
    __shared__ float4 WpbV[HB*16];                 // Wpb * SCALEV
    __shared__ float coefH[HB], invH[HB];
    __shared__ float pci[3];
    __shared__ int rowValid;

    const int ni = blockIdx.x;
    const int n = ni >> 9, i = ni & 511;
    const int t = threadIdx.x;
    const int w = t >> 5, l = t & 31;
    const int jl = w*8 + (l >> 2);      // phase-1 j within tile
    const int csub = l & 3;             // c-quarter; also selects 3 heads
    const int h0 = csub*3;

    const size_t zrow = (size_t)ni * LB * CB;
    const size_t LL = (size_t)LB*LB;
    const size_t lbase0 = (size_t)(n*HB)*LL + (size_t)i*LB;

    // prologue: issue tile 0
    {
        const float* src = z + zrow;
#pragma unroll
        for (int r = 0; r < 4; r++) {
            int chunk = t + 256*r;
            int row = chunk >> 4, c16 = chunk & 15;
            cp_async16(&zb[0][row*ZS + c16*4], src + row*64 + c16*4);
        }
        CP_COMMIT();
    }

    // init (visible via first in-loop __syncthreads)
    if (t < 192) {
        float4 wv = __ldg(((const float4*)Wpb) + t);
        WpbV[t] = make_float4(wv.x*SCALEV, wv.y*SCALEV, wv.z*SCALEV, wv.w*SCALEV);
    }
    if (t < HB) {
        float g = gamma_raw[t];
        coefH[t] = -log1pf(__expf(g)) * SQ29V * 0.5f * SCALEV;
    }
    if (t < 3) pci[t] = pCB[(size_t)ni*3 + t];
    if (t == 0) rowValid = g_mask[ni];

    float2 az[12];
#pragma unroll
    for (int h = 0; h < 12; h++) az[h] = make_float2(0.f, 0.f);
    float sloc[3] = {0.f, 0.f, 0.f};

    for (int jt = 0; jt < 8; jt++) {
        const int buf = jt & 1;
        const float* zs = zb[buf];
        const int j0 = jt*TJ;

        CP_WAIT0();
        __syncthreads();
        if (jt < 7) {
            const float* src = z + zrow + (size_t)(j0 + TJ)*64;
            float* dst = zb[buf^1];
#pragma unroll
            for (int r = 0; r < 4; r++) {
                int chunk = t + 256*r;
                int row = chunk >> 4, c16 = chunk & 15;
                cp_async16(&dst[row*ZS + c16*4], src + row*64 + c16*4);
            }
            CP_COMMIT();
        }

        // ---- phase 1: logits + exp for j = j0 + jl ----
        const int j = j0 + jl;
        // independent early loads (node logits for my 3 heads, geometry, mask)
        float nodeA0 = __ldg(g_alpha + lbase0 + (size_t)(h0+0)*LL + j);
        float nodeA1 = __ldg(g_alpha + lbase0 + (size_t)(h0+1)*LL + j);
        float nodeA2 = __ldg(g_alpha + lbase0 + (size_t)(h0+2)*LL + j);
        const float* pj = pCB + (size_t)(n*LB + j)*3;
        float dx = __ldg(pj+0)-pci[0], dy = __ldg(pj+1)-pci[1], dz = __ldg(pj+2)-pci[2];
        float d2 = dx*dx + dy*dy + dz*dz;
        float mf = (rowValid && __ldg(&g_mask[n*LB + j])) ? 0.f : -INFV;

        float4 zc[4];
#pragma unroll
        for (int k = 0; k < 4; k++)
            zc[k] = *(const float4*)(zs + jl*ZS + (csub + 4*k)*4);

        float acc[12];
#pragma unroll
        for (int h = 0; h < 12; h++) {
            float a = 0.f;
#pragma unroll
            for (int k = 0; k < 4; k++) {
                float4 wv = WpbV[h*16 + csub + 4*k];
                float4 zv = zc[k];
                a += zv.x*wv.x + zv.y*wv.y + zv.z*wv.z + zv.w*wv.w;
            }
            acc[h] = a;
        }
        // butterfly: all 4 lanes of this j get the full pair sum
#pragma unroll
        for (int h = 0; h < 12; h++) {
            acc[h] += __shfl_xor_sync(0xffffffffu, acc[h], 1);
            acc[h] += __shfl_xor_sync(0xffffffffu, acc[h], 2);
        }
        // each lane finalizes its 3 heads
        {
            float lo0 = nodeA0 + coefH[h0+0]*d2 + acc[h0+0] + mf;
            float lo1 = nodeA1 + coefH[h0+1]*d2 + acc[h0+1] + mf;
            float lo2 = nodeA2 + coefH[h0+2]*d2 + acc[h0+2] + mf;
            float e0 = __expf(lo0), e1 = __expf(lo1), e2 = __expf(lo2);
            sloc[0] += e0; sloc[1] += e1; sloc[2] += e2;
            lg[jl*12 + h0 + 0] = e0;
            lg[jl*12 + h0 + 1] = e1;
            lg[jl*12 + h0 + 2] = e2;
            float* ga = g_alpha + lbase0 + j;
            ga[(size_t)(h0+0)*LL] = e0;
            ga[(size_t)(h0+1)*LL] = e1;
            ga[(size_t)(h0+2)*LL] = e2;
        }
        __syncwarp();

        // ---- phase 2: az += e · z over my warp's 8 j (warp-local lg rows) ----
#pragma unroll
        for (int jj = 0; jj < 8; jj++) {
            int rl = w*8 + jj;
            float2 zv = *(const float2*)(zs + rl*ZS + l*2);
            const float4* p4 = (const float4*)(lg + rl*12);
            float4 pa = p4[0], pb = p4[1], pc = p4[2];
            az[0].x  += pa.x*zv.x; az[0].y  += pa.x*zv.y;
            az[1].x  += pa.y*zv.x; az[1].y  += pa.y*zv.y;
            az[2].x  += pa.z*zv.x; az[2].y  += pa.z*zv.y;
            az[3].x  += pa.w*zv.x; az[3].y  += pa.w*zv.y;
            az[4].x  += pb.x*zv.x; az[4].y  += pb.x*zv.y;
            az[5].x  += pb.y*zv.x; az[5].y  += pb.y*zv.y;
            az[6].x  += pb.z*zv.x; az[6].y  += pb.z*zv.y;
            az[7].x  += pb.w*zv.x; az[7].y  += pb.w*zv.y;
            az[8].x  += pc.x*zv.x; az[8].y  += pc.x*zv.y;
            az[9].x  += pc.y*zv.x; az[9].y  += pc.y*zv.y;
            az[10].x += pc.z*zv.x; az[10].y += pc.z*zv.y;
            az[11].x += pc.w*zv.x; az[11].y += pc.w*zv.y;
        }
    }
    __syncthreads();

    // ---- per-head sums: sloc partials -> invH, g_inv (reuse lg as [12][64]) ----
#pragma unroll
    for (int hh = 0; hh < 3; hh++)
        lg[(h0+hh)*64 + jl] = sloc[hh];
    __syncthreads();
    // 8 warps cover 12 heads: warp w handles heads w, w+8
    for (int h = w; h < HB; h += 8) {
        float s = lg[h*64 + l] + lg[h*64 + 32 + l];
#pragma unroll
        for (int off = 16; off; off >>= 1) s += __shfl_xor_sync(0xffffffffu, s, off);
        if (l == 0) {
            float inv = rowValid ? (1.f/s) : 0.f;
            invH[h] = inv;
            g_inv[(size_t)ni*HB + h] = inv;
        }
    }
    __syncthreads();

    // ---- normalize az, reduce 8 warp-partials via zb scratch ----
#pragma unroll
    for (int h = 0; h < 12; h++) {
        float inv = invH[h];
        az[h].x *= inv; az[h].y *= inv;
    }
    float* part = &zb[0][0];   // 8 x 768 = 24 KB scratch
#pragma unroll
    for (int h = 0; h < 12; h++)
        ((float2*)(part + w*768 + h*64))[l] = az[h];
    __syncthreads();

    float* fo = g_featsP + (size_t)ni*FEATP;
    for (int o = t; o < 768; o += 256) {
        float v = part[o] + part[768+o] + part[1536+o] + part[2304+o]
                + part[3072+o] + part[3840+o] + part[4608+o] + part[5376+o];
        fo[o] = v;
    }
    if (t < FEATP - FEAT) fo[FEAT + t] = 0.f;   // zero pad
}

// ---------------------------------------------------------------------------
// C4: feat_node (alpha·v) + accP (alpha·pCB) per (n,h); unnormalized e from
// g_alpha, scaled by g_inv at the end.
// ---------------------------------------------------------------------------
__global__ __launch_bounds__(320) void av_kernel(const float* __restrict__ pCB)
{
    __shared__ float As[64*65];
    __shared__ float vs[64*16];
    __shared__ float ps[64*4];
    int b = blockIdx.x;
    int nh = b >> 3;
    int i0 = (b & 7)*64;
    int n = nh / HB, h = nh - n*HB;
    int t = threadIdx.x;
    int i_l = t & 63, col = t >> 6;

    float a0 = 0.f, a1 = 0.f, a2 = 0.f, a3 = 0.f;

    for (int jt = 0; jt < 8; jt++) {
        int j0 = jt*64;
        __syncthreads();
        if (t < 256) {
            int r = t >> 2, c16 = t & 3;
            const float4* src = (const float4*)(g_alpha + ((size_t)nh*LB + i0 + r)*LB + j0 + c16*16);
#pragma unroll
            for (int q = 0; q < 4; q++) {
                float4 v = __ldg(src + q);
                int jj = c16*16 + q*4;
                As[(jj+0)*65 + r] = v.x;
                As[(jj+1)*65 + r] = v.y;
                As[(jj+2)*65 + r] = v.z;
                As[(jj+3)*65 + r] = v.w;
            }
            *(float4*)(vs + r*16 + c16*4) =
                *(const float4*)(g_vh + ((size_t)nh*LB + j0 + r)*DB + c16*4);
        } else {
            int tt = t - 256;
            const float* pb = pCB + (size_t)(n*LB + j0 + tt)*3;
            ps[tt*4+0] = pb[0]; ps[tt*4+1] = pb[1]; ps[tt*4+2] = pb[2]; ps[tt*4+3] = 0.f;
        }
        __syncthreads();

        if (col < 4) {
#pragma unroll 8
            for (int j = 0; j < 64; j++) {
                float a = As[j*65 + i_l];
                float4 vv = *(float4*)(vs + j*16 + col*4);
                a0 += a*vv.x; a1 += a*vv.y; a2 += a*vv.z; a3 += a*vv.w;
            }
        } else {
#pragma unroll 8
            for (int j = 0; j < 64; j++) {
                float a = As[j*65 + i_l];
                float4 pp = *(float4*)(ps + j*4);
                a0 += a*pp.x; a1 += a*pp.y; a2 += a*pp.z;
            }
        }
    }

    int i = i0 + i_l;
    float inv = __ldg(&g_inv[(size_t)(n*LB + i)*HB + h]);
    if (col < 4) {
        float* fo = g_featsP + (size_t)(n*LB + i)*FEATP + 768 + h*16 + col*4;
        fo[0] = a0*inv; fo[1] = a1*inv; fo[2] = a2*inv; fo[3] = a3*inv;
    } else {
        float* ap = g_accP + ((size_t)nh*LB + i)*3;
        ap[0] = a0*inv; ap[1] = a1*inv; ap[2] = a2*inv;
    }
}

// ---------------------------------------------------------------------------
// C5: spatial features. One thread per (n,i,h).
// ---------------------------------------------------------------------------
__global__ __launch_bounds__(256) void spatial_kernel(
    const float* __restrict__ R,
    const float* __restrict__ tvec)
{
    int gid = blockIdx.x*256 + threadIdx.x;
    int ni = gid / HB, h = gid - ni*HB;
    int n = ni >> 9;
    const float* ap = g_accP + ((size_t)(n*HB + h)*LB + (ni & 511))*3;
    float a0 = ap[0] - tvec[(size_t)ni*3+0];
    float a1 = ap[1] - tvec[(size_t)ni*3+1];
    float a2 = ap[2] - tvec[(size_t)ni*3+2];
    const float* Rp = R + (size_t)ni*9;
    float l0 = Rp[0]*a0 + Rp[3]*a1 + Rp[6]*a2;
    float l1 = Rp[1]*a0 + Rp[4]*a1 + Rp[7]*a2;
    float l2 = Rp[2]*a0 + Rp[5]*a1 + Rp[8]*a2;
    float dist = sqrtf(l0*l0 + l1*l1 + l2*l2);
    float idn = 1.0f / (dist + 1e-4f);
    float* fo = g_featsP + (size_t)ni*FEATP + 960;
    fo[h*3+0] = l0; fo[h*3+1] = l1; fo[h*3+2] = l2;
    fo[36 + h] = dist;
    fo[48 + h*3+0] = l0*idn; fo[48 + h*3+1] = l1*idn; fo[48 + h*3+2] = l2*idn;
}

// ---------------------------------------------------------------------------
// D1: output projection tiled GEMM.
// ---------------------------------------------------------------------------
#define KT 64
#define NKT (FEATP/KT)
#define TS 68
#define CP_WAIT1()  asm volatile("cp.async.wait_group 1;\n")

__global__ __launch_bounds__(256) void proj_kernel(
    const float* __restrict__ x,
    const float* __restrict__ bout)
{
    __shared__ float fsT[2][32*TS];
    __shared__ float wsT[2][32*TS];
    int t = threadIdx.x;
    int mb = blockIdx.x & 31, fb = blockIdx.x >> 5;
    int r0 = mb*32, f0 = fb*32;

    const float* fbase = g_featsP + (size_t)r0*FEATP;
    const float* wbase = g_WoutP  + (size_t)f0*FEATP;
    {
#pragma unroll
        for (int rep = 0; rep < 2; rep++) {
            int idx = t + rep*256;
            int row = idx >> 4, col = idx & 15;
            cp_async16(&fsT[0][row*TS + col*4], fbase + (size_t)row*FEATP + col*4);
            cp_async16(&wsT[0][row*TS + col*4], wbase + (size_t)row*FEATP + col*4);
        }
        CP_COMMIT();
    }

    int tr = t >> 4, tf = t & 15;
    float a00 = 0.f, a01 = 0.f, a10 = 0.f, a11 = 0.f;
    for (int kt = 0; kt < NKT; kt++) {
        int buf = kt & 1;
        if (kt < NKT-1) {
#pragma unroll
            for (int rep = 0; rep < 2; rep++) {
                int idx = t + rep*256;
                int row = idx >> 4, col = idx & 15;
                cp_async16(&fsT[buf^1][row*TS + col*4],
                           fbase + (size_t)row*FEATP + (kt+1)*KT + col*4);
                cp_async16(&wsT[buf^1][row*TS + col*4],
                           wbase + (size_t)row*FEATP + (kt+1)*KT + col*4);
            }
            CP_COMMIT();
            CP_WAIT1();
        } else {
            CP_WAIT0();
        }
        __syncthreads();

        const float4* fr0 = (const float4*)&fsT[buf][(tr*2  )*TS];
        const float4* fr1 = (const float4*)&fsT[buf][(tr*2+1)*TS];
        const float4* wr0 = (const float4*)&wsT[buf][(tf*2  )*TS];
        const float4* wr1 = (const float4*)&wsT[buf][(tf*2+1)*TS];
#pragma unroll
        for (int k4 = 0; k4 < KT/4; k4++) {
            float4 xa = fr0[k4], xb = fr1[k4];
            float4 wa = wr0[k4], wb = wr1[k4];
            a00 += xa.x*wa.x + xa.y*wa.y + xa.z*wa.z + xa.w*wa.w;
            a01 += xa.x*wb.x + xa.y*wb.y + xa.z*wb.z + xa.w*wb.w;
            a10 += xb.x*wa.x + xb.y*wa.y + xb.z*wa.z + xb.w*wa.w;
            a11 += xb.x*wb.x + xb.y*wb.y + xb.z*wb.z + xb.w*wb.w;
        }
        __syncthreads();
    }

    int ri0 = r0 + tr*2, ri1 = ri0 + 1;
    int fA = f0 + tf*2, fB2 = fA + 1;
    float bA = __ldg(&bout[fA]), bB = __ldg(&bout[fB2]);
    int m0 = g_mask[ri0], m1 = g_mask[ri1];
    g_y[(size_t)ri0*FB + fA ] = x[(size_t)ri0*FB + fA ] + (m0 ? (a00 + bA) : 0.f);
    g_y[(size_t)ri0*FB + fB2] = x[(size_t)ri0*FB + fB2] + (m0 ? (a01 + bB) : 0.f);
    g_y[(size_t)ri1*FB + fA ] = x[(size_t)ri1*FB + fA ] + (m1 ? (a10 + bA) : 0.f);
    g_y[(size_t)ri1*FB + fB2] = x[(size_t)ri1*FB + fB2] + (m1 ? (a11 + bB) : 0.f);
}

// ---------------------------------------------------------------------------
// D2: LayerNorm.
// ---------------------------------------------------------------------------
__global__ __launch_bounds__(256) void ln_kernel(
    const float* __restrict__ lnw,
    const float* __restrict__ lnb,
    float* __restrict__ out)
{
    int t = threadIdx.x;
    int wid = t >> 5, lane = t & 31;
    int ri = blockIdx.x * 8 + wid;
    const float* yr = g_y + (size_t)ri*FB;
    float v0 = yr[lane], v1 = yr[lane+32], v2 = yr[lane+64], v3 = yr[lane+96];
    float s = v0 + v1 + v2 + v3;
#pragma unroll
    for (int off = 16; off; off >>= 1) s += __shfl_xor_sync(0xffffffffu, s, off);
    float mu = s * (1.0f/128.0f);
    float d0 = v0-mu, d1 = v1-mu, d2 = v2-mu, d3 = v3-mu;
    float sq = d0*d0 + d1*d1 + d2*d2 + d3*d3;
#pragma unroll
    for (int off = 16; off; off >>= 1) sq += __shfl_xor_sync(0xffffffffu, sq, off);
    float rstd = rsqrtf(sq * (1.0f/128.0f) + 1e-5f);
    out[(size_t)ri*FB + lane     ] = d0*rstd*lnw[lane     ] + lnb[lane     ];
    out[(size_t)ri*FB + lane + 32] = d1*rstd*lnw[lane + 32] + lnb[lane + 32];
    out[(size_t)ri*FB + lane + 64] = d2*rstd*lnw[lane + 64] + lnb[lane + 64];
    out[(size_t)ri*FB + lane + 96] = d3*rstd*lnw[lane + 96] + lnb[lane + 96];
}

extern "C" void kernel_launch(void* const* d_in, const int* in_sizes, int n_in,
                              void* d_out, int out_size) {
    const float* R    = (const float*)d_in[0];
    const float* tv   = (const float*)d_in[1];
    const float* pCB  = (const float*)d_in[2];
    const float* x    = (const float*)d_in[3];
    const float* z    = (const float*)d_in[4];
    const void*  mask = d_in[5];
    const float* Wq   = (const float*)d_in[6];
    const float* Wk   = (const float*)d_in[7];
    const float* Wv   = (const float*)d_in[8];
    const float* Wpb  = (const float*)d_in[9];
    const float* gr   = (const float*)d_in[10];
    const float* Wout = (const float*)d_in[11];
    const float* bo   = (const float*)d_in[12];
    const float* lnw  = (const float*)d_in[13];
    const float* lnb  = (const float*)d_in[14];
    float* out = (float*)d_out;

    decode_mask_kernel<<<1, NL>>>(mask);
    prepw_kernel<<<FB, 256>>>(Wout);
    qkv_kernel<<<NL/8, 576>>>(x, Wq, Wk, Wv);
    qk_kernel<<<NH*64, 256>>>();
    fused_pz_kernel<<<NL, 256>>>(pCB, z, Wpb, gr);
    av_kernel<<<NH*8, 320>>>(pCB);
    spatial_kernel<<<NL*HB/256, 256>>>(R, tv);
    proj_kernel<<<128, 256>>>(x, bo);
    ln_kernel<<<NL/8, 256>>>(lnw, lnb, out);
}

// round 15
// speedup vs baseline: 1.0662x; 1.0662x over previous
#include <cuda_runtime.h>
#include <math.h>

#define NB 2
#define LB 512
#define FB 128
#define CB 64
#define HB 12
#define DB 16
#define NL (NB*LB)               // 1024
#define NH (NB*HB)               // 24
#define FEAT 1044
#define FEATP 1088
#define INFV 100000.0f
#define SQ29V 0.47140452079103173f
#define SCALEV 0.57735026918962576f

__device__ float g_qh[(size_t)NH*LB*DB];     // [n][h][i][d]  (q pre-scaled by SCALEV)
__device__ float g_kh[(size_t)NH*LB*DB];
__device__ float g_vh[(size_t)NH*LB*DB];
__device__ int   g_mask[NL];
__device__ float g_alpha[(size_t)NH*LB*LB];  // node logits -> unnormalized exp(alpha)
__device__ float g_inv[(size_t)NL*HB];       // 1/S per (n,i,h); 0 for invalid rows
__device__ float g_accP[(size_t)NH*LB*3];
__device__ float g_featsP[(size_t)NL*FEATP];
__device__ float g_WoutP[(size_t)FB*FEATP];
__device__ float g_y[(size_t)NL*FB];

__device__ __forceinline__ void cp_async16(void* smem_dst, const void* gmem_src) {
    unsigned s = (unsigned)__cvta_generic_to_shared(smem_dst);
    asm volatile("cp.async.cg.shared.global [%0], [%1], 16;\n" :: "r"(s), "l"(gmem_src));
}
#define CP_COMMIT() asm volatile("cp.async.commit_group;\n")
#define CP_WAIT0()  asm volatile("cp.async.wait_group 0;\n")
#define CP_WAIT1()  asm volatile("cp.async.wait_group 1;\n")

// ---------------------------------------------------------------------------
// A: decode mask of ambiguous serialized dtype (bool/int32/fp32).
// ---------------------------------------------------------------------------
__global__ void decode_mask_kernel(const void* __restrict__ mraw) {
    __shared__ int cnt[4];
    int t = threadIdx.x;
    if (t < 4) cnt[t] = 0;
    __syncthreads();
    const unsigned char* b = (const unsigned char*)mraw;
    unsigned char v = b[t];
    if (v) atomicAdd(&cnt[t & 3], 1);
    __syncthreads();
    int m;
    if (cnt[1] | cnt[2] | cnt[3]) {
        if (cnt[0]) m = (b[t] != 0);
        else        m = (((const float*)mraw)[t] != 0.0f);
    } else {
        if (cnt[0]) m = (((const int*)mraw)[t] != 0);
        else        m = 0;
    }
    g_mask[t] = m;
}

// ---------------------------------------------------------------------------
// A2: zero-padded Wout copy.
// ---------------------------------------------------------------------------
__global__ void prepw_kernel(const float* __restrict__ Wout) {
    int f = blockIdx.x;
    for (int k = threadIdx.x; k < FEATP; k += 256)
        g_WoutP[(size_t)f*FEATP + k] = (k < FEAT) ? Wout[(size_t)f*FEAT + k] : 0.f;
}

// ---------------------------------------------------------------------------
// B: QKV projection -> per-head layouts [n][h][idx][d]. q scaled by SCALEV.
// ---------------------------------------------------------------------------
__global__ __launch_bounds__(576) void qkv_kernel(
    const float* __restrict__ x,
    const float* __restrict__ Wq,
    const float* __restrict__ Wk,
    const float* __restrict__ Wv)
{
    __shared__ float xs[8][FB];
    int t = threadIdx.x;
    int r0 = blockIdx.x * 8;
    for (int idx = t; idx < 8*FB; idx += 576)
        xs[idx >> 7][idx & 127] = x[(size_t)r0*FB + idx];
    __syncthreads();

    int which = t / 192;
    int o = t - which*192;
    const float* W = (which == 0) ? Wq : (which == 1) ? Wk : Wv;
    float* outp    = (which == 0) ? g_qh : (which == 1) ? g_kh : g_vh;
    const float4* W4 = (const float4*)(W + (size_t)o*FB);

    float acc[8];
#pragma unroll
    for (int r = 0; r < 8; r++) acc[r] = 0.f;
    for (int kk = 0; kk < FB/4; kk++) {
        float4 w = __ldg(&W4[kk]);
#pragma unroll
        for (int r = 0; r < 8; r++) {
            float4 xv = *(const float4*)&xs[r][kk*4];
            acc[r] += w.x*xv.x + w.y*xv.y + w.z*xv.z + w.w*xv.w;
        }
    }
    float scale = (which == 0) ? SCALEV : 1.0f;
    int h = o >> 4, d = o & 15;
#pragma unroll
    for (int r = 0; r < 8; r++) {
        int row = r0 + r;
        int n = row >> 9, i = row & 511;
        outp[((size_t)(n*HB + h)*LB + i)*DB + d] = acc[r] * scale;
    }
}

// ---------------------------------------------------------------------------
// C1: node logits GEMM. Per (n,h): [512x16]x[16x512] -> g_alpha (scaled dots).
// ---------------------------------------------------------------------------
__global__ __launch_bounds__(256) void qk_kernel()
{
    __shared__ float Qs[64*17], Ks[64*17];
    int b = blockIdx.x;
    int nh = b >> 6, tile = b & 63;
    int i0 = (tile >> 3)*64, j0 = (tile & 7)*64;
    int t = threadIdx.x;
    {
        int r = t >> 2, c4 = t & 3;
        float4 qv = *(const float4*)(g_qh + ((size_t)nh*LB + i0 + r)*DB + c4*4);
        Qs[r*17+c4*4+0]=qv.x; Qs[r*17+c4*4+1]=qv.y; Qs[r*17+c4*4+2]=qv.z; Qs[r*17+c4*4+3]=qv.w;
        float4 kv = *(const float4*)(g_kh + ((size_t)nh*LB + j0 + r)*DB + c4*4);
        Ks[r*17+c4*4+0]=kv.x; Ks[r*17+c4*4+1]=kv.y; Ks[r*17+c4*4+2]=kv.z; Ks[r*17+c4*4+3]=kv.w;
    }
    __syncthreads();
    int ti = t >> 4, tj = t & 15;
    float acc[4][4];
#pragma unroll
    for (int a = 0; a < 4; a++)
#pragma unroll
        for (int bb = 0; bb < 4; bb++) acc[a][bb] = 0.f;
    const float* Qb = Qs + (ti*4)*17;
    const float* Kb = Ks + (tj*4)*17;
#pragma unroll
    for (int d = 0; d < 16; d++) {
        float q0=Qb[d], q1=Qb[17+d], q2=Qb[34+d], q3=Qb[51+d];
        float k0=Kb[d], k1=Kb[17+d], k2=Kb[34+d], k3=Kb[51+d];
        acc[0][0]+=q0*k0; acc[0][1]+=q0*k1; acc[0][2]+=q0*k2; acc[0][3]+=q0*k3;
        acc[1][0]+=q1*k0; acc[1][1]+=q1*k1; acc[1][2]+=q1*k2; acc[1][3]+=q1*k3;
        acc[2][0]+=q2*k0; acc[2][1]+=q2*k1; acc[2][2]+=q2*k2; acc[2][3]+=q2*k3;
        acc[3][0]+=q3*k0; acc[3][1]+=q3*k1; acc[3][2]+=q3*k2; acc[3][3]+=q3*k3;
    }
    float* outb = g_alpha + ((size_t)nh*LB + i0 + ti*4)*LB + j0 + tj*4;
#pragma unroll
    for (int k = 0; k < 4; k++) {
        float4 o = make_float4(acc[k][0], acc[k][1], acc[k][2], acc[k][3]);
        *(float4*)(outb + (size_t)k*LB) = o;
    }
}

// ---------------------------------------------------------------------------
// C2: FUSED pair-bias + exp + sums + alpha·z per (n,i). Two-pass (R11-proven
// structure), widened to 512 threads: pass A handles ONE j per thread
// (12 accumulators, no spill pressure, 32 warps/SM at 2 blocks); pass B is
// 16 j-groups x 32 j with an extra 16->8 partial-merge stage via lg.
// Max-free softmax with deferred normalization (g_inv).
// ---------------------------------------------------------------------------
__global__ __launch_bounds__(512, 2) void fused_pz_kernel(
    const float* __restrict__ pCB,
    const float* __restrict__ z,
    const float* __restrict__ Wpb,
    const float* __restrict__ gamma_raw)
{
    __shared__ __align__(16) float lg[LB*HB];   // e values [j][12], 24 KB
    __shared__ float4 WpbV[HB*16];              // Wpb * SCALEV
    __shared__ float coefH[HB], invH[HB];
    __shared__ float pci[3];
    __shared__ int rowValid;

    const int ni = blockIdx.x;
    const int n = ni >> 9, i = ni & 511;
    const int t = threadIdx.x;
    const int w = t >> 5, l = t & 31;

    if (t < 192) {
        float4 wv = __ldg(((const float4*)Wpb) + t);
        WpbV[t] = make_float4(wv.x*SCALEV, wv.y*SCALEV, wv.z*SCALEV, wv.w*SCALEV);
    }
    if (t < HB) {
        float g = gamma_raw[t];
        coefH[t] = -log1pf(__expf(g)) * SQ29V * 0.5f * SCALEV;
    }
    if (t < 3) pci[t] = pCB[(size_t)ni*3 + t];
    if (t == 0) rowValid = g_mask[ni];
    __syncthreads();

    const size_t zrow = (size_t)ni * LB * CB;
    const size_t LL = (size_t)LB*LB;
    const size_t lbase0 = (size_t)(n*HB)*LL + (size_t)i*LB;
    const int j = t;                 // 512 threads = 512 j, one pass

    // ---- pass A: logits -> e for j ----
    {
        float acc[12];
#pragma unroll
        for (int h = 0; h < 12; h++)
            acc[h] = __ldg(g_alpha + lbase0 + (size_t)h*LL + j);

        const float* pj = pCB + (size_t)(n*LB + j)*3;
        float dx = __ldg(pj+0)-pci[0], dy = __ldg(pj+1)-pci[1], dz = __ldg(pj+2)-pci[2];
        float d2 = dx*dx + dy*dy + dz*dz;
        float mf = (rowValid && __ldg(&g_mask[n*LB + j])) ? 0.f : -INFV;

        const float4* z4 = (const float4*)(z + zrow + (size_t)j*CB);
#pragma unroll 4
        for (int c4 = 0; c4 < 16; c4++) {
            float4 a = __ldg(z4 + c4);
#pragma unroll
            for (int h = 0; h < 12; h++) {
                float4 wv = WpbV[h*16 + c4];
                acc[h] += a.x*wv.x + a.y*wv.y + a.z*wv.z + a.w*wv.w;
            }
        }
        float e[12];
#pragma unroll
        for (int h = 0; h < 12; h++)
            e[h] = __expf(acc[h] + coefH[h]*d2 + mf);

        // lg store: j*12 floats (48B) is 16B-aligned for every j
        float4* dst = (float4*)(lg + j*12);
        dst[0] = make_float4(e[0], e[1], e[2],  e[3]);
        dst[1] = make_float4(e[4], e[5], e[6],  e[7]);
        dst[2] = make_float4(e[8], e[9], e[10], e[11]);
        float* ga = g_alpha + lbase0 + j;
#pragma unroll
        for (int h = 0; h < 12; h++)
            ga[(size_t)h*LL] = e[h];
    }
    __syncthreads();

    // ---- per-head sums over lg -> invH / g_inv (12 of 16 warps) ----
    if (w < HB) {
        float s = 0.f;
        for (int jj = l; jj < LB; jj += 32) s += lg[jj*12 + w];
#pragma unroll
        for (int off = 16; off; off >>= 1) s += __shfl_xor_sync(0xffffffffu, s, off);
        if (l == 0) {
            float inv = rowValid ? (1.f/s) : 0.f;
            invH[w] = inv;
            g_inv[(size_t)ni*HB + w] = inv;
        }
    }
    __syncthreads();

    // ---- pass B: e · z (z re-read -> L2 hits), 16 groups x 32 j ----
    float2 az[12];
#pragma unroll
    for (int h = 0; h < 12; h++) az[h] = make_float2(0.f, 0.f);
    const float2* z2 = (const float2*)(z + zrow);

#pragma unroll 4
    for (int jj = 0; jj < 32; jj++) {
        int j2 = w*32 + jj;
        float2 zv = __ldg(z2 + (size_t)j2*32 + l);
        const float4* p4 = (const float4*)(lg + j2*12);
        float4 pa = p4[0], pb = p4[1], pc = p4[2];
        az[0].x  += pa.x*zv.x; az[0].y  += pa.x*zv.y;
        az[1].x  += pa.y*zv.x; az[1].y  += pa.y*zv.y;
        az[2].x  += pa.z*zv.x; az[2].y  += pa.z*zv.y;
        az[3].x  += pa.w*zv.x; az[3].y  += pa.w*zv.y;
        az[4].x  += pb.x*zv.x; az[4].y  += pb.x*zv.y;
        az[5].x  += pb.y*zv.x; az[5].y  += pb.y*zv.y;
        az[6].x  += pb.z*zv.x; az[6].y  += pb.z*zv.y;
        az[7].x  += pb.w*zv.x; az[7].y  += pb.w*zv.y;
        az[8].x  += pc.x*zv.x; az[8].y  += pc.x*zv.y;
        az[9].x  += pc.y*zv.x; az[9].y  += pc.y*zv.y;
        az[10].x += pc.z*zv.x; az[10].y += pc.z*zv.y;
        az[11].x += pc.w*zv.x; az[11].y += pc.w*zv.y;
    }
#pragma unroll
    for (int h = 0; h < 12; h++) {
        float inv = invH[h];
        az[h].x *= inv; az[h].y *= inv;
    }
    __syncthreads();   // all e reads done; lg reusable as reduce buffer

    // ---- merge 16 partials -> 8 via lg, then final 8-way sum ----
    float* part = lg;  // [8][768] = 24 KB, exactly lg
    if (w >= 8) {
#pragma unroll
        for (int h = 0; h < 12; h++)
            ((float2*)(part + (w-8)*768 + h*64))[l] = az[h];
    }
    __syncthreads();
    if (w < 8) {
#pragma unroll
        for (int h = 0; h < 12; h++) {
            float2 p = ((float2*)(part + w*768 + h*64))[l];
            az[h].x += p.x; az[h].y += p.y;
            ((float2*)(part + w*768 + h*64))[l] = az[h];
        }
    }
    __syncthreads();

    float* fo = g_featsP + (size_t)ni*FEATP;
    for (int o = t; o < 768; o += 512) {
        float v = part[o] + part[768+o] + part[1536+o] + part[2304+o]
                + part[3072+o] + part[3840+o] + part[4608+o] + part[5376+o];
        fo[o] = v;
    }
    if (t < FEATP - FEAT) fo[FEAT + t] = 0.f;   // zero pad
}

// ---------------------------------------------------------------------------
// C4: feat_node (alpha·v) + accP (alpha·pCB) per (n,h); unnormalized e from
// g_alpha, scaled by g_inv at the end.
// ---------------------------------------------------------------------------
__global__ __launch_bounds__(320) void av_kernel(const float* __restrict__ pCB)
{
    __shared__ float As[64*65];
    __shared__ float vs[64*16];
    __shared__ float ps[64*4];
    int b = blockIdx.x;
    int nh = b >> 3;
    int i0 = (b & 7)*64;
    int n = nh / HB, h = nh - n*HB;
    int t = threadIdx.x;
    int i_l = t & 63, col = t >> 6;

    float a0 = 0.f, a1 = 0.f, a2 = 0.f, a3 = 0.f;

    for (int jt = 0; jt < 8; jt++) {
        int j0 = jt*64;
        __syncthreads();
        if (t < 256) {
            int r = t >> 2, c16 = t & 3;
            const float4* src = (const float4*)(g_alpha + ((size_t)nh*LB + i0 + r)*LB + j0 + c16*16);
#pragma unroll
            for (int q = 0; q < 4; q++) {
                float4 v = __ldg(src + q);
                int jj = c16*16 + q*4;
                As[(jj+0)*65 + r] = v.x;
                As[(jj+1)*65 + r] = v.y;
                As[(jj+2)*65 + r] = v.z;
                As[(jj+3)*65 + r] = v.w;
            }
            *(float4*)(vs + r*16 + c16*4) =
                *(const float4*)(g_vh + ((size_t)nh*LB + j0 + r)*DB + c16*4);
        } else {
            int tt = t - 256;
            const float* pb = pCB + (size_t)(n*LB + j0 + tt)*3;
            ps[tt*4+0] = pb[0]; ps[tt*4+1] = pb[1]; ps[tt*4+2] = pb[2]; ps[tt*4+3] = 0.f;
        }
        __syncthreads();

        if (col < 4) {
#pragma unroll 8
            for (int j = 0; j < 64; j++) {
                float a = As[j*65 + i_l];
                float4 vv = *(float4*)(vs + j*16 + col*4);
                a0 += a*vv.x; a1 += a*vv.y; a2 += a*vv.z; a3 += a*vv.w;
            }
        } else {
#pragma unroll 8
            for (int j = 0; j < 64; j++) {
                float a = As[j*65 + i_l];
                float4 pp = *(float4*)(ps + j*4);
                a0 += a*pp.x; a1 += a*pp.y; a2 += a*pp.z;
            }
        }
    }

    int i = i0 + i_l;
    float inv = __ldg(&g_inv[(size_t)(n*LB + i)*HB + h]);
    if (col < 4) {
        float* fo = g_featsP + (size_t)(n*LB + i)*FEATP + 768 + h*16 + col*4;
        fo[0] = a0*inv; fo[1] = a1*inv; fo[2] = a2*inv; fo[3] = a3*inv;
    } else {
        float* ap = g_accP + ((size_t)nh*LB + i)*3;
        ap[0] = a0*inv; ap[1] = a1*inv; ap[2] = a2*inv;
    }
}

// ---------------------------------------------------------------------------
// C5: spatial features. One thread per (n,i,h).
// ---------------------------------------------------------------------------
__global__ __launch_bounds__(256) void spatial_kernel(
    const float* __restrict__ R,
    const float* __restrict__ tvec)
{
    int gid = blockIdx.x*256 + threadIdx.x;
    int ni = gid / HB, h = gid - ni*HB;
    int n = ni >> 9;
    const float* ap = g_accP + ((size_t)(n*HB + h)*LB + (ni & 511))*3;
    float a0 = ap[0] - tvec[(size_t)ni*3+0];
    float a1 = ap[1] - tvec[(size_t)ni*3+1];
    float a2 = ap[2] - tvec[(size_t)ni*3+2];
    const float* Rp = R + (size_t)ni*9;
    float l0 = Rp[0]*a0 + Rp[3]*a1 + Rp[6]*a2;
    float l1 = Rp[1]*a0 + Rp[4]*a1 + Rp[7]*a2;
    float l2 = Rp[2]*a0 + Rp[5]*a1 + Rp[8]*a2;
    float dist = sqrtf(l0*l0 + l1*l1 + l2*l2);
    float idn = 1.0f / (dist + 1e-4f);
    float* fo = g_featsP + (size_t)ni*FEATP + 960;
    fo[h*3+0] = l0; fo[h*3+1] = l1; fo[h*3+2] = l2;
    fo[36 + h] = dist;
    fo[48 + h*3+0] = l0*idn; fo[48 + h*3+1] = l1*idn; fo[48 + h*3+2] = l2*idn;
}

// ---------------------------------------------------------------------------
// D1: output projection tiled GEMM.
// ---------------------------------------------------------------------------
#define KT 64
#define NKT (FEATP/KT)
#define TS 68

__global__ __launch_bounds__(256) void proj_kernel(
    const float* __restrict__ x,
    const float* __restrict__ bout)
{
    __shared__ float fsT[2][32*TS];
    __shared__ float wsT[2][32*TS];
    int t = threadIdx.x;
    int mb = blockIdx.x & 31, fb = blockIdx.x >> 5;
    int r0 = mb*32, f0 = fb*32;

    const float* fbase = g_featsP + (size_t)r0*FEATP;
    const float* wbase = g_WoutP  + (size_t)f0*FEATP;
    {
#pragma unroll
        for (int rep = 0; rep < 2; rep++) {
            int idx = t + rep*256;
            int row = idx >> 4, col = idx & 15;
            cp_async16(&fsT[0][row*TS + col*4], fbase + (size_t)row*FEATP + col*4);
            cp_async16(&wsT[0][row*TS + col*4], wbase + (size_t)row*FEATP + col*4);
        }
        CP_COMMIT();
    }

    int tr = t >> 4, tf = t & 15;
    float a00 = 0.f, a01 = 0.f, a10 = 0.f, a11 = 0.f;
    for (int kt = 0; kt < NKT; kt++) {
        int buf = kt & 1;
        if (kt < NKT-1) {
#pragma unroll
            for (int rep = 0; rep < 2; rep++) {
                int idx = t + rep*256;
                int row = idx >> 4, col = idx & 15;
                cp_async16(&fsT[buf^1][row*TS + col*4],
                           fbase + (size_t)row*FEATP + (kt+1)*KT + col*4);
                cp_async16(&wsT[buf^1][row*TS + col*4],
                           wbase + (size_t)row*FEATP + (kt+1)*KT + col*4);
            }
            CP_COMMIT();
            CP_WAIT1();
        } else {
            CP_WAIT0();
        }
        __syncthreads();

        const float4* fr0 = (const float4*)&fsT[buf][(tr*2  )*TS];
        const float4* fr1 = (const float4*)&fsT[buf][(tr*2+1)*TS];
        const float4* wr0 = (const float4*)&wsT[buf][(tf*2  )*TS];
        const float4* wr1 = (const float4*)&wsT[buf][(tf*2+1)*TS];
#pragma unroll
        for (int k4 = 0; k4 < KT/4; k4++) {
            float4 xa = fr0[k4], xb = fr1[k4];
            float4 wa = wr0[k4], wb = wr1[k4];
            a00 += xa.x*wa.x + xa.y*wa.y + xa.z*wa.z + xa.w*wa.w;
            a01 += xa.x*wb.x + xa.y*wb.y + xa.z*wb.z + xa.w*wb.w;
            a10 += xb.x*wa.x + xb.y*wa.y + xb.z*wa.z + xb.w*wa.w;
            a11 += xb.x*wb.x + xb.y*wb.y + xb.z*wb.z + xb.w*wb.w;
        }
        __syncthreads();
    }

    int ri0 = r0 + tr*2, ri1 = ri0 + 1;
    int fA = f0 + tf*2, fB2 = fA + 1;
    float bA = __ldg(&bout[fA]), bB = __ldg(&bout[fB2]);
    int m0 = g_mask[ri0], m1 = g_mask[ri1];
    g_y[(size_t)ri0*FB + fA ] = x[(size_t)ri0*FB + fA ] + (m0 ? (a00 + bA) : 0.f);
    g_y[(size_t)ri0*FB + fB2] = x[(size_t)ri0*FB + fB2] + (m0 ? (a01 + bB) : 0.f);
    g_y[(size_t)ri1*FB + fA ] = x[(size_t)ri1*FB + fA ] + (m1 ? (a10 + bA) : 0.f);
    g_y[(size_t)ri1*FB + fB2] = x[(size_t)ri1*FB + fB2] + (m1 ? (a11 + bB) : 0.f);
}

// ---------------------------------------------------------------------------
// D2: LayerNorm.
// ---------------------------------------------------------------------------
__global__ __launch_bounds__(256) void ln_kernel(
    const float* __restrict__ lnw,
    const float* __restrict__ lnb,
    float* __restrict__ out)
{
    int t = threadIdx.x;
    int wid = t >> 5, lane = t & 31;
    int ri = blockIdx.x * 8 + wid;
    const float* yr = g_y + (size_t)ri*FB;
    float v0 = yr[lane], v1 = yr[lane+32], v2 = yr[lane+64], v3 = yr[lane+96];
    float s = v0 + v1 + v2 + v3;
#pragma unroll
    for (int off = 16; off; off >>= 1) s += __shfl_xor_sync(0xffffffffu, s, off);
    float mu = s * (1.0f/128.0f);
    float d0 = v0-mu, d1 = v1-mu, d2 = v2-mu, d3 = v3-mu;
    float sq = d0*d0 + d1*d1 + d2*d2 + d3*d3;
#pragma unroll
    for (int off = 16; off; off >>= 1) sq += __shfl_xor_sync(0xffffffffu, sq, off);
    float rstd = rsqrtf(sq * (1.0f/128.0f) + 1e-5f);
    out[(size_t)ri*FB + lane     ] = d0*rstd*lnw[lane     ] + lnb[lane     ];
    out[(size_t)ri*FB + lane + 32] = d1*rstd*lnw[lane + 32] + lnb[lane + 32];
    out[(size_t)ri*FB + lane + 64] = d2*rstd*lnw[lane + 64] + lnb[lane + 64];
    out[(size_t)ri*FB + lane + 96] = d3*rstd*lnw[lane + 96] + lnb[lane + 96];
}

extern "C" void kernel_launch(void* const* d_in, const int* in_sizes, int n_in,
                              void* d_out, int out_size) {
    const float* R    = (const float*)d_in[0];
    const float* tv   = (const float*)d_in[1];
    const float* pCB  = (const float*)d_in[2];
    const float* x    = (const float*)d_in[3];
    const float* z    = (const float*)d_in[4];
    const void*  mask = d_in[5];
    const float* Wq   = (const float*)d_in[6];
    const float* Wk   = (const float*)d_in[7];
    const float* Wv   = (const float*)d_in[8];
    const float* Wpb  = (const float*)d_in[9];
    const float* gr   = (const float*)d_in[10];
    const float* Wout = (const float*)d_in[11];
    const float* bo   = (const float*)d_in[12];
    const float* lnw  = (const float*)d_in[13];
    const float* lnb  = (const float*)d_in[14];
    float* out = (float*)d_out;

    decode_mask_kernel<<<1, NL>>>(mask);
    prepw_kernel<<<FB, 256>>>(Wout);
    qkv_kernel<<<NL/8, 576>>>(x, Wq, Wk, Wv);
    qk_kernel<<<NH*64, 256>>>();
    fused_pz_kernel<<<NL, 512>>>(pCB, z, Wpb, gr);
    av_kernel<<<NH*8, 320>>>(pCB);
    spatial_kernel<<<NL*HB/256, 256>>>(R, tv);
    proj_kernel<<<128, 256>>>(x, bo);
    ln_kernel<<<NL/8, 256>>>(lnw, lnb, out);
}